// round 7
// baseline (speedup 1.0000x reference)
#include <cuda_runtime.h>
#include <cstdint>

// GIKDWConv: depthwise 7x7 conv, stride 1, pad 3, 4-fold-rotation-symmetrized
// weights. N=16, C=384, H=W=64, fp32.
//
// R7: persistent strided pipeline. Grid = 148*5 = 740 blocks; 6144 half-tile
// work items assigned block-strided (8-9 per block), continuously
// double-buffered with cp.async (tile + raw weights for item i+1 stream in
// while item i computes). Kills the 20% wave-tail quantization of the 3072-
// block version and amortizes the load prologue 4x. Compute core unchanged:
// 8 rows x 2 cols per thread, channel pairs packed in f32x2 (fma.rn.f32x2),
// 13 unique symmetrized weights.

#define HH 64
#define WW 64
#define NN 16
#define CC 384
#define TR 38              // tile rows: 32 output + 6 halo
#define TC 70              // tile cols: 64 output + 6 halo
#define CELLS (TR * TC)    // 2660
#define RPT 8              // output rows per thread
#define ITEMS 6144         // 3072 (n,cp) pairs x 2 vertical halves
#define NBLK 740           // 148 SMs x 5 CTAs
typedef unsigned long long ull;

// orbit id of each (ky,kx) tap under 90-degree rotation (13 unique weights)
__device__ constexpr int ORBIT[7][7] = {
    {0, 1, 2, 3, 4, 5, 0},
    {5, 6, 7, 8, 9, 6, 1},
    {4, 9,10,11,10, 7, 2},
    {3, 8,11,12,11, 8, 3},
    {2, 7,10,11,10, 9, 4},
    {1, 6, 9, 8, 7, 6, 5},
    {0, 5, 4, 3, 2, 1, 0}};
__device__ constexpr int REP_I[13] = {0,0,0,0,0,0,1,1,1,1,2,2,3};
__device__ constexpr int REP_J[13] = {0,1,2,3,4,5,1,2,3,4,2,3,3};

__device__ __forceinline__ ull fma2(ull a, ull b, ull c) {
    ull d;
    asm("fma.rn.f32x2 %0, %1, %2, %3;" : "=l"(d) : "l"(a), "l"(b), "l"(c));
    return d;
}
__device__ __forceinline__ ull pack2(float lo, float hi) {
    ull r;
    asm("mov.b64 %0, {%1, %2};" : "=l"(r) : "f"(lo), "f"(hi));
    return r;
}
__device__ __forceinline__ void unpack2(ull v, float& lo, float& hi) {
    asm("mov.b64 {%0, %1}, %2;" : "=f"(lo), "=f"(hi) : "l"(v));
}
__device__ __forceinline__ uint32_t s2u(const void* p) {
    uint32_t a;
    asm("{ .reg .u64 t; cvta.to.shared.u64 t, %1; cvt.u32.u64 %0, t; }"
        : "=r"(a) : "l"(p));
    return a;
}
// 4-byte cp.async with zfill: sz=4 copies, sz=0 writes zeros (no src access)
__device__ __forceinline__ void cp4(uint32_t d, const float* s, int sz) {
    asm volatile("cp.async.ca.shared.global [%0], [%1], 4, %2;"
                 :: "r"(d), "l"(s), "r"(sz));
}
__device__ __forceinline__ void cp8(uint32_t d, const float* s) {
    asm volatile("cp.async.ca.shared.global [%0], [%1], 8;"
                 :: "r"(d), "l"(s));
}

struct Buf {
    ull   sx[CELLS];   // packed (c0,c1) half-tile
    float wraw[98];    // raw weights: c0[49], c1[49]
    float pad[2];
};

__global__ __launch_bounds__(128, 5)
void gik_dwconv_kernel(const float* __restrict__ x,
                       const float* __restrict__ weight,
                       float* __restrict__ out) {
    __shared__ Buf buf[2];             // 2 x 21.9 KB
    __shared__ ull swsym[2][13];       // symmetrized packed weights per buffer

    const int tid = threadIdx.x;

    // ---- async loader for item id into buffer b ----
    auto load_item = [&](int id, int b) {
        const int t  = id & 1;
        const int pc = id >> 1;
        const int n  = pc / 192;
        const int cp = pc - n * 192;
        const float* x0 = x + ((n * CC + cp * 2) * (HH * WW));
        const float* x1 = x0 + HH * WW;
        const int gy0 = t * 32 - 3;
        const uint32_t dst0 = s2u(buf[b].sx);
        #pragma unroll 3
        for (int idx = tid; idx < CELLS; idx += 128) {
            int r  = idx / TC;
            int c  = idx - r * TC;
            int gy = gy0 + r, gx = c - 3;
            int v  = ((unsigned)gy < (unsigned)HH) &
                     ((unsigned)gx < (unsigned)WW);
            int off = v ? (gy * WW + gx) : 0;
            int sz  = v ? 4 : 0;
            cp4(dst0 + idx * 8,     x0 + off, sz);
            cp4(dst0 + idx * 8 + 4, x1 + off, sz);
        }
        if (tid < 49)   // 98 floats as 49 8-byte cps (8B-aligned both sides)
            cp8(s2u(buf[b].wraw) + tid * 8, weight + cp * 98 + tid * 2);
        asm volatile("cp.async.commit_group;" ::: "memory");
    };

    const int cx = (tid & 31) * 2;     // even output column 0..62
    const int r0 = (tid >> 5) * RPT;   // local output row base: 0,8,16,24

    load_item(blockIdx.x, 0);

    int b = 0;
    for (int id = blockIdx.x; id < ITEMS; id += NBLK) {
        const int nxt = id + NBLK;
        const bool hn = nxt < ITEMS;
        if (hn) {
            load_item(nxt, b ^ 1);
            asm volatile("cp.async.wait_group 1;" ::: "memory");
        } else {
            asm volatile("cp.async.wait_group 0;" ::: "memory");
        }
        __syncthreads();               // tile + raw weights of item id ready

        // symmetrize weights for this item
        if (tid < 13) {
            const int i = REP_I[tid], j = REP_J[tid];
            const float* w0 = buf[b].wraw;
            const float* w1 = w0 + 49;
            float a0 = 0.25f * (w0[i*7 + j] + w0[j*7 + (6-i)] +
                                w0[(6-i)*7 + (6-j)] + w0[(6-j)*7 + i]);
            float a1 = 0.25f * (w1[i*7 + j] + w1[j*7 + (6-i)] +
                                w1[(6-i)*7 + (6-j)] + w1[(6-j)*7 + i]);
            swsym[b][tid] = pack2(a0, a1);
        }
        __syncthreads();

        ull wreg[13];
        #pragma unroll
        for (int o = 0; o < 13; o++) wreg[o] = swsym[b][o];

        ull acc0[RPT], acc1[RPT];      // col cx and cx+1
        #pragma unroll
        for (int r = 0; r < RPT; r++) { acc0[r] = 0ull; acc1[r] = 0ull; }

        const ull* sb = buf[b].sx;
        #pragma unroll
        for (int y = 0; y < RPT + 6; y++) {
            ull xv[8];                 // 8 packed inputs: 4x LDS.128
            {
                const ulonglong2* rp =
                    (const ulonglong2*)(sb + (r0 + y) * TC + cx);
                #pragma unroll
                for (int q = 0; q < 4; q++) {
                    ulonglong2 v = rp[q];
                    xv[2*q] = v.x; xv[2*q+1] = v.y;
                }
            }
            #pragma unroll
            for (int k = 0; k < 7; k++) {
                const int r = y - k;
                if (r >= 0 && r < RPT) {
                    #pragma unroll
                    for (int u = 0; u < 7; u++) {
                        const ull w = wreg[ORBIT[k][u]];
                        acc0[r] = fma2(w, xv[u],     acc0[r]);
                        acc1[r] = fma2(w, xv[u + 1], acc1[r]);
                    }
                }
            }
        }

        // ---- store: float2 per channel-row ----
        {
            const int t  = id & 1;
            const int pc = id >> 1;
            const int n  = pc / 192;
            const int cp = pc - n * 192;
            float* o0 = out + ((n * CC + cp * 2) * (HH * WW)) + t * 32 * WW;
            float* o1 = o0 + HH * WW;
            #pragma unroll
            for (int r = 0; r < RPT; r++) {
                float a, bb, c, d;
                unpack2(acc0[r], a, bb);   // a: c0 col cx,   bb: c1 col cx
                unpack2(acc1[r], c, d);    // c: c0 col cx+1, d: c1 col cx+1
                const int off = (r0 + r) * WW + cx;
                *(float2*)(o0 + off) = make_float2(a, c);
                *(float2*)(o1 + off) = make_float2(bb, d);
            }
        }
        __syncthreads();               // all reads of buf[b] done before reuse
        b ^= 1;
    }
}

extern "C" void kernel_launch(void* const* d_in, const int* in_sizes, int n_in,
                              void* d_out, int out_size) {
    const float* x = (const float*)d_in[0];       // [16,384,64,64]
    const float* w = (const float*)d_in[1];       // [384,1,7,7]
    float* out = (float*)d_out;                   // [16,384,64,64]
    gik_dwconv_kernel<<<NBLK, 128>>>(x, w, out);
}

// round 8
// speedup vs baseline: 1.2192x; 1.2192x over previous
#include <cuda_runtime.h>
#include <cstdint>

// GIKDWConv: depthwise 7x7 conv, stride 1, pad 3, 4-fold-rotation-symmetrized
// weights. N=16, C=384, H=W=64, fp32.
//
// R8: R6 structure (block = one (n, channel-pair), two 32-row halves,
// cp.async double buffer, 5 CTAs/SM) with the half-1 prefetch INTERLEAVED
// into the half-0 compute loop as 21 slices of 128 cells, so LDGSTS/ALU
// issue slots hide in the FFMA2 rt gaps instead of bursting behind a
// barrier. One div per slice instead of per cell.

#define HH 64
#define WW 64
#define NN 16
#define CC 384
#define TR 38              // tile rows: 32 output + 6 halo
#define TC 70              // tile cols: 64 output + 6 halo
#define CELLS (TR * TC)    // 2660
#define NSLICE 21          // ceil(2660/128)
#define RPT 8              // output rows per thread
typedef unsigned long long ull;

// orbit id of each (ky,kx) tap under 90-degree rotation (13 unique weights)
__device__ constexpr int ORBIT[7][7] = {
    {0, 1, 2, 3, 4, 5, 0},
    {5, 6, 7, 8, 9, 6, 1},
    {4, 9,10,11,10, 7, 2},
    {3, 8,11,12,11, 8, 3},
    {2, 7,10,11,10, 9, 4},
    {1, 6, 9, 8, 7, 6, 5},
    {0, 5, 4, 3, 2, 1, 0}};
__device__ constexpr int REP_I[13] = {0,0,0,0,0,0,1,1,1,1,2,2,3};
__device__ constexpr int REP_J[13] = {0,1,2,3,4,5,1,2,3,4,2,3,3};

__device__ __forceinline__ ull fma2(ull a, ull b, ull c) {
    ull d;
    asm("fma.rn.f32x2 %0, %1, %2, %3;" : "=l"(d) : "l"(a), "l"(b), "l"(c));
    return d;
}
__device__ __forceinline__ ull pack2(float lo, float hi) {
    ull r;
    asm("mov.b64 %0, {%1, %2};" : "=l"(r) : "f"(lo), "f"(hi));
    return r;
}
__device__ __forceinline__ void unpack2(ull v, float& lo, float& hi) {
    asm("mov.b64 {%0, %1}, %2;" : "=f"(lo), "=f"(hi) : "l"(v));
}
__device__ __forceinline__ uint32_t s2u(const void* p) {
    uint32_t a;
    asm("{ .reg .u64 t; cvta.to.shared.u64 t, %1; cvt.u32.u64 %0, t; }"
        : "=r"(a) : "l"(p));
    return a;
}
// 4-byte cp.async with zfill: sz=4 copies, sz=0 writes zeros (no src access)
__device__ __forceinline__ void cp4(uint32_t d, const float* s, int sz) {
    asm volatile("cp.async.ca.shared.global [%0], [%1], 4, %2;"
                 :: "r"(d), "l"(s), "r"(sz));
}

__global__ __launch_bounds__(128, 5)
void gik_dwconv_kernel(const float* __restrict__ x,
                       const float* __restrict__ weight,
                       float* __restrict__ out) {
    __shared__ ull sx[2 * CELLS];   // double-buffered packed half-tiles
    __shared__ ull sw[13];          // packed symmetric weights

    const int tid = threadIdx.x;
    const int cp  = blockIdx.x;         // channel pair 0..191
    const int n   = blockIdx.y;         // batch 0..15
    const int c0  = cp * 2;

    const float* x0 = x + ((n * CC + c0) * (HH * WW));
    const float* x1 = x0 + HH * WW;
    const uint32_t sbase = s2u(sx);

    // one 128-cell slice of a half-tile load (interleaved-packed cp.async)
    auto slice = [&](int s, uint32_t dst0, int gy0) {
        int cell = s * 128 + tid;
        if (cell < CELLS) {
            int r  = cell / TC;
            int c  = cell - r * TC;
            int gy = gy0 + r, gx = c - 3;
            int v  = ((unsigned)gy < (unsigned)HH) &
                     ((unsigned)gx < (unsigned)WW);
            int off = v ? (gy * WW + gx) : 0;
            int sz  = v ? 4 : 0;
            cp4(dst0 + cell * 8,     x0 + off, sz);
            cp4(dst0 + cell * 8 + 4, x1 + off, sz);
        }
    };

    // ---- prologue: load half 0 into buffer 0 ----
    #pragma unroll
    for (int s = 0; s < NSLICE; s++) slice(s, sbase, -3);
    asm volatile("cp.async.commit_group;" ::: "memory");

    // ---- the 13 unique symmetrized weights (LDG overlaps the cp.async) ----
    if (tid < 13) {
        const int i = REP_I[tid], j = REP_J[tid];
        const float* w0 = weight + c0 * 49;
        const float* w1 = w0 + 49;
        float a0 = 0.25f * (w0[i*7 + j] + w0[j*7 + (6-i)] +
                            w0[(6-i)*7 + (6-j)] + w0[(6-j)*7 + i]);
        float a1 = 0.25f * (w1[i*7 + j] + w1[j*7 + (6-i)] +
                            w1[(6-i)*7 + (6-j)] + w1[(6-j)*7 + i]);
        sw[tid] = pack2(a0, a1);
    }

    const int cx = (tid & 31) * 2;     // even output column 0..62
    const int r0 = (tid >> 5) * RPT;   // local output row base: 0,8,16,24

    asm volatile("cp.async.wait_group 0;" ::: "memory");
    __syncthreads();                   // half 0 + weights visible

    ull wreg[13];
    #pragma unroll
    for (int o = 0; o < 13; o++) wreg[o] = sw[o];

    #pragma unroll
    for (int t = 0; t < 2; t++) {
        const ull* sb = sx + t * CELLS;

        ull acc0[RPT], acc1[RPT];      // col cx and cx+1
        #pragma unroll
        for (int r = 0; r < RPT; r++) { acc0[r] = 0ull; acc1[r] = 0ull; }

        #pragma unroll
        for (int y = 0; y < RPT + 6; y++) {
            ull xv[8];                 // 8 packed inputs: 4x LDS.128
            {
                const ulonglong2* rp =
                    (const ulonglong2*)(sb + (r0 + y) * TC + cx);
                #pragma unroll
                for (int q = 0; q < 4; q++) {
                    ulonglong2 v = rp[q];
                    xv[2*q] = v.x; xv[2*q+1] = v.y;
                }
            }
            // interleaved prefetch of half 1 into buffer 1 (t=0 only):
            // slices y and y+14 — LDGSTS issue hides in FFMA2 rt gaps
            if (t == 0) {
                slice(y, sbase + CELLS * 8, 29);
                if (y < NSLICE - 14) slice(y + 14, sbase + CELLS * 8, 29);
            }
            #pragma unroll
            for (int k = 0; k < 7; k++) {
                const int r = y - k;
                if (r >= 0 && r < RPT) {
                    #pragma unroll
                    for (int u = 0; u < 7; u++) {
                        const ull w = wreg[ORBIT[k][u]];
                        acc0[r] = fma2(w, xv[u],     acc0[r]);
                        acc1[r] = fma2(w, xv[u + 1], acc1[r]);
                    }
                }
            }
        }
        if (t == 0)
            asm volatile("cp.async.commit_group;" ::: "memory");

        // ---- store: float2 per channel-row ----
        float* o0 = out + ((n * CC + c0) * (HH * WW)) + t * 32 * WW;
        float* o1 = o0 + HH * WW;
        #pragma unroll
        for (int r = 0; r < RPT; r++) {
            float a, b, c, d;
            unpack2(acc0[r], a, b);     // a: c0 col cx,   b: c1 col cx
            unpack2(acc1[r], c, d);     // c: c0 col cx+1, d: c1 col cx+1
            const int off = (r0 + r) * WW + cx;
            *(float2*)(o0 + off) = make_float2(a, c);
            *(float2*)(o1 + off) = make_float2(b, d);
        }
        if (t == 0) {
            asm volatile("cp.async.wait_group 0;" ::: "memory");
            __syncthreads();           // half 1 fully resident in buffer 1
        }
    }
}

extern "C" void kernel_launch(void* const* d_in, const int* in_sizes, int n_in,
                              void* d_out, int out_size) {
    const float* x = (const float*)d_in[0];       // [16,384,64,64]
    const float* w = (const float*)d_in[1];       // [384,1,7,7]
    float* out = (float*)d_out;                   // [16,384,64,64]
    dim3 grid(CC / 2, NN);
    gik_dwconv_kernel<<<grid, 128>>>(x, w, out);
}